// round 17
// baseline (speedup 1.0000x reference)
#include <cuda_runtime.h>
#include <math.h>

#define B_     64
#define S_EN_  50
#define S_DE_  50
#define H_     32
#define EMB_E_ 64
#define EMB_D_ 32
#define DE_V_  19000
#define NGRP   8
#define GSZ    16
#define NBLK   128
#define NTH    256

typedef unsigned long long ull;

// ---------------- device-global scratch ----------------
__device__ ull g_keys[S_DE_][NGRP][8];                  // per-step per-group per-row argmax keys
__device__ float g_hc[2 * H_ * B_];                     // encoder handoff: h1[k][b], c1[k][b]
__device__ unsigned g_gcnt[S_DE_][NGRP], g_gready[S_DE_][NGRP];
__device__ unsigned g_ecnt = 0, g_eready = 0;
__device__ unsigned g_cnt = 0, g_gen = 0;               // init barrier only

// ---------------- dynamic smem offsets (bytes) ----------------
#define OFF_WF    0         // fc tile floats [32][NC], NC<=1188 -> 152064
#define OFF_WB2   152064    // fc_b pairs u64 [594] -> 4752
#define OFF_WIH   156816    // dWih [128][32] f -> 16384
#define OFF_WHH   173200    // dWhh [128][32] f -> 16384
#define OFF_BIAS  189584    // dbih+dbhh [128] f -> 512
#define OFF_H2    190096    // (h,h) packed u64 [32][9] -> 2304
#define OFF_C     192400    // c [8][32] f -> 1024
#define OFF_G     193424    // gates [8][132] f -> 4224
#define OFF_X     197648    // x [8][32] f -> 1024
#define OFF_RED   198672    // per-warp argmax [8][8] u64 -> 512
#define OFF_TOK   199184    // tokens [8] int -> 32
#define SMEM_BYTES 199232

// ---------------- helpers ----------------
__device__ __forceinline__ ull pack2(float lo, float hi) {
    ull r; asm("mov.b64 %0, {%1, %2};" : "=l"(r) : "f"(lo), "f"(hi)); return r;
}
__device__ __forceinline__ float2 unpack2(ull v) {
    float2 r; asm("mov.b64 {%0, %1}, %2;" : "=f"(r.x), "=f"(r.y) : "l"(v)); return r;
}
__device__ __forceinline__ void fma2(ull& d, ull a, ull b) {
    asm("fma.rn.f32x2 %0, %1, %2, %0;" : "+l"(d) : "l"(a), "l"(b));
}
__device__ __forceinline__ float sigmoidf_(float x) { return 1.0f / (1.0f + expf(-x)); }

// larger key == (bigger value, then smaller index) -> matches jnp.argmax
__device__ __forceinline__ ull amax_key(float f, int v) {
    unsigned u = __float_as_uint(f);
    u = (u & 0x80000000u) ? ~u : (u | 0x80000000u);
    return ((ull)u << 32) | (ull)(0xFFFFFFFFu - (unsigned)v);
}
__device__ __forceinline__ unsigned ld_acq(const unsigned* p) {
    unsigned v;
    asm volatile("ld.acquire.gpu.global.u32 %0, [%1];" : "=r"(v) : "l"(p) : "memory");
    return v;
}
__device__ __forceinline__ void st_rel(unsigned* p, unsigned v) {
    asm volatile("st.release.gpu.global.u32 [%0], %1;" :: "l"(p), "r"(v) : "memory");
}
__device__ __forceinline__ void red_max64(ull* p, ull v) {
    asm volatile("red.relaxed.gpu.global.max.u64 [%0], %1;" :: "l"(p), "l"(v) : "memory");
}
__device__ __forceinline__ void spin_until(const unsigned* p) {
    while (ld_acq(p) == 0u) {}
}

// one-time init barrier (replay-safe)
__device__ __forceinline__ void grid_barrier() {
    __threadfence();
    __syncthreads();
    if (threadIdx.x == 0) {
        unsigned my = *(volatile unsigned*)&g_gen;
        __threadfence();
        if (atomicAdd(&g_cnt, 1u) == NBLK - 1) {
            g_cnt = 0;
            __threadfence();
            atomicAdd(&g_gen, 1u);
        } else {
            while (*(volatile unsigned*)&g_gen == my) { __nanosleep(32); }
        }
    }
    __syncthreads();
}

__global__ void __launch_bounds__(NTH, 1)
seq2seq_kernel(const int* __restrict__ en_batch, const int* __restrict__ en_lens,
               const int* __restrict__ de_batch,
               const float* __restrict__ en_emb,
               const float* __restrict__ eWih, const float* __restrict__ eWhh,
               const float* __restrict__ ebih, const float* __restrict__ ebhh,
               const float* __restrict__ de_emb,
               const float* __restrict__ dWih, const float* __restrict__ dWhh,
               const float* __restrict__ dbih, const float* __restrict__ dbhh,
               const float* __restrict__ fcW, const float* __restrict__ fcb,
               float* __restrict__ out)
{
    extern __shared__ __align__(16) char dynsm[];
    float* sWf    = (float*)(dynsm + OFF_WF);
    ull*   sWb2   = (ull*)  (dynsm + OFF_WB2);
    float* sWih   = (float*)(dynsm + OFF_WIH);
    float* sWhh   = (float*)(dynsm + OFF_WHH);
    float* sBiasf = (float*)(dynsm + OFF_BIAS);
    ull*   sH2p   = (ull*)  (dynsm + OFF_H2);     // [32][9] stride-9
    float* sCf    = (float*)(dynsm + OFF_C);
    float* sGf    = (float*)(dynsm + OFF_G);      // [8][132]
    float* sXf    = (float*)(dynsm + OFF_X);      // [8][32]
    ull*   sRed   = (ull*)  (dynsm + OFF_RED);    // [8 warps][8 rows]
    int*   sTok   = (int*)  (dynsm + OFF_TOK);

    // encoder static smem
    __shared__ float eX[EMB_E_];
    __shared__ float ePart[2][4 * H_];
    __shared__ float eBias[4 * H_];
    __shared__ float e_h[H_], e_c[H_];
    __shared__ int   eToks[S_EN_];

    const int tid  = threadIdx.x;
    const int bk   = blockIdx.x;
    const int g    = bk >> 4;        // group 0..7
    const int m    = bk & 15;        // member 0..15
    const int wid  = tid >> 5;
    const int lane = tid & 31;

    // tile: members 0..13 get 1188 cols, 14..15 get 1184
    const int NC   = (m < 14) ? 1188 : 1184;
    const int NP   = NC >> 1;
    const int col0 = (m < 14) ? m * 1188 : 16632 + (m - 14) * 1184;

    // ---------- phase 0: zero out[:,0,:] for this tile (all 64 rows), sync state ----------
    for (int i = tid; i < B_ * NC; i += NTH) {
        int r = i / NC, c = i % NC;
        out[(size_t)(r * S_DE_) * DE_V_ + col0 + c] = 0.0f;
    }
    {
        int gt = bk * NTH + tid;
        if (gt < S_DE_ * NGRP * 8) ((ull*)g_keys)[gt] = 0ull;
        if (gt < S_DE_ * NGRP) { (&g_gcnt[0][0])[gt] = 0u; (&g_gready[0][0])[gt] = 0u; }
        if (gt == 0) { g_ecnt = 0u; g_eready = 0u; }
    }

    // ---------- load fc tile, biases, decoder LSTM weights into smem ----------
    for (int i = tid; i < NC * H_; i += NTH)          // sWf[k][c] = fcW[col0+c][k]
        sWf[(i & 31) * NC + (i >> 5)] = fcW[(size_t)col0 * H_ + i];
    for (int p = tid; p < NP; p += NTH)
        sWb2[p] = pack2(fcb[col0 + 2 * p], fcb[col0 + 2 * p + 1]);
    for (int i = tid; i < 128 * 32; i += NTH) { sWih[i] = dWih[i]; sWhh[i] = dWhh[i]; }
    if (tid < 128) sBiasf[tid] = dbih[tid] + dbhh[tid];

    grid_barrier();     // zeroed flags visible chip-wide before any set/poll

    // ---------- encoder + first decoder LSTM: blocks 0..63, one row each ----------
    if (bk < B_) {
        float wreg[48];
        const int jg = tid & 127, hf = tid >> 7;
        #pragma unroll
        for (int k = 0; k < 32; k++) wreg[k] = eWih[jg * EMB_E_ + hf * 32 + k];
        #pragma unroll
        for (int k = 0; k < 16; k++) wreg[32 + k] = eWhh[jg * H_ + hf * 16 + k];
        if (tid < 4 * H_) eBias[tid] = ebih[tid] + ebhh[tid];
        if (tid < H_) { e_h[tid] = 0.0f; e_c[tid] = 0.0f; }
        if (tid < S_EN_) eToks[tid] = en_batch[bk * S_EN_ + tid];
        __syncthreads();

        const int len = en_lens[bk];
        float xr = 0.0f;
        if (tid < EMB_E_ && len > 0) xr = en_emb[(size_t)eToks[0] * EMB_E_ + tid];
        for (int t = 0; t < len; t++) {
            if (tid < EMB_E_) eX[tid] = xr;
            __syncthreads();
            if (tid < EMB_E_ && t + 1 < len)
                xr = en_emb[(size_t)eToks[t + 1] * EMB_E_ + tid];
            {
                float p = 0.0f;
                #pragma unroll
                for (int k = 0; k < 32; k++) p += eX[hf * 32 + k] * wreg[k];
                #pragma unroll
                for (int k = 0; k < 16; k++) p += e_h[hf * 16 + k] * wreg[32 + k];
                ePart[hf][jg] = p;
            }
            __syncthreads();
            if (tid < H_) {
                float gi = ePart[0][tid]          + ePart[1][tid]          + eBias[tid];
                float gf = ePart[0][H_ + tid]     + ePart[1][H_ + tid]     + eBias[H_ + tid];
                float gg = ePart[0][2 * H_ + tid] + ePart[1][2 * H_ + tid] + eBias[2 * H_ + tid];
                float go = ePart[0][3 * H_ + tid] + ePart[1][3 * H_ + tid] + eBias[3 * H_ + tid];
                float ig = sigmoidf_(gi), fg = sigmoidf_(gf), og = sigmoidf_(go);
                float c  = fg * e_c[tid] + ig * tanhf(gg);
                e_c[tid] = c;
                e_h[tid] = og * tanhf(c);
            }
            __syncthreads();
        }

        // first decoder step (token = de_batch[:,0]); weights from smem tables
        {
            int tok = de_batch[bk * S_DE_];
            if (tid < EMB_D_) eX[tid] = de_emb[(size_t)tok * EMB_D_ + tid];
            __syncthreads();
            {
                const float* src = hf ? e_h : eX;
                const float* wsm = hf ? &sWhh[jg * 32] : &sWih[jg * 32];
                float p = 0.0f;
                #pragma unroll
                for (int k = 0; k < 32; k++) p += src[k] * wsm[k];
                ePart[hf][jg] = p;
            }
            __syncthreads();
            if (tid < H_) {
                float gi = ePart[0][tid]          + ePart[1][tid]          + sBiasf[tid];
                float gf = ePart[0][H_ + tid]     + ePart[1][H_ + tid]     + sBiasf[H_ + tid];
                float gg = ePart[0][2 * H_ + tid] + ePart[1][2 * H_ + tid] + sBiasf[2 * H_ + tid];
                float go = ePart[0][3 * H_ + tid] + ePart[1][3 * H_ + tid] + sBiasf[3 * H_ + tid];
                float ig = sigmoidf_(gi), fg = sigmoidf_(gf), og = sigmoidf_(go);
                float c  = fg * e_c[tid] + ig * tanhf(gg);
                float h  = og * tanhf(c);
                __stcg(&g_hc[tid * B_ + bk], h);               // h1[k][b]
                __stcg(&g_hc[H_ * B_ + tid * B_ + bk], c);     // c1[k][b]
            }
            __syncwarp();
            if (tid == 0) {
                __threadfence();
                if (atomicAdd(&g_ecnt, 1u) == B_ - 1) st_rel(&g_eready, 1u);
            }
        }
    }

    // ---------- all blocks: wait for handoff, load group rows into smem ----------
    if (tid == 0) spin_until(&g_eready);
    __syncthreads();
    if (tid < H_ * 8) {                              // h1 -> sH2 [k][9] packed
        int k = tid >> 3, r = tid & 7;
        float v = __ldcg(&g_hc[k * B_ + g * 8 + r]);
        sH2p[k * 9 + r] = pack2(v, v);
    }
    if (tid < 8 * H_) {                              // c1 -> sC [r][32]
        int r = tid >> 5, hd = tid & 31;
        sCf[r * 32 + hd] = __ldcg(&g_hc[H_ * B_ + hd * B_ + g * 8 + r]);
    }
    __syncthreads();

    const ull* sWp = (const ull*)sWf;                // pair view [32][NP]
    const bool has3 = (tid + 512 < NP);

    for (int s = 1; s < S_DE_; s++) {
        const bool last = (s == S_DE_ - 1);

        // ================= logits GEMM: 8 rows x NC cols =================
        ull acc0[8], acc1[8], acc2[8];
        {
            ull b0 = sWb2[tid], b1 = sWb2[tid + 256];
            ull b2 = has3 ? sWb2[tid + 512] : 0ull;
            #pragma unroll
            for (int r = 0; r < 8; r++) { acc0[r] = b0; acc1[r] = b1; acc2[r] = b2; }
        }
        for (int k = 0; k < H_; k++) {
            const ull* hrow = &sH2p[k * 9];
            ull h0 = hrow[0], h1 = hrow[1], h2 = hrow[2], h3 = hrow[3];
            ull h4 = hrow[4], h5 = hrow[5], h6 = hrow[6], h7 = hrow[7];
            const ull* wk = sWp + k * NP;
            ull w0 = wk[tid], w1 = wk[tid + 256];
            fma2(acc0[0], h0, w0); fma2(acc0[1], h1, w0); fma2(acc0[2], h2, w0); fma2(acc0[3], h3, w0);
            fma2(acc0[4], h4, w0); fma2(acc0[5], h5, w0); fma2(acc0[6], h6, w0); fma2(acc0[7], h7, w0);
            fma2(acc1[0], h0, w1); fma2(acc1[1], h1, w1); fma2(acc1[2], h2, w1); fma2(acc1[3], h3, w1);
            fma2(acc1[4], h4, w1); fma2(acc1[5], h5, w1); fma2(acc1[6], h6, w1); fma2(acc1[7], h7, w1);
            if (has3) {
                ull w2 = wk[tid + 512];
                fma2(acc2[0], h0, w2); fma2(acc2[1], h1, w2); fma2(acc2[2], h2, w2); fma2(acc2[3], h3, w2);
                fma2(acc2[4], h4, w2); fma2(acc2[5], h5, w2); fma2(acc2[6], h6, w2); fma2(acc2[7], h7, w2);
            }
        }

        // ================= argmax -> group keys -> arrive =================
        if (!last) {
            const int c0a = col0 + 2 * tid;
            const int c0b = col0 + 2 * (tid + 256);
            const int c0c = col0 + 2 * (tid + 512);
            ull kr[8];
            #pragma unroll
            for (int r = 0; r < 8; r++) {
                float2 va = unpack2(acc0[r]);
                float2 vb = unpack2(acc1[r]);
                ull best = amax_key(va.x, c0a);
                ull k2;
                k2 = amax_key(va.y, c0a + 1); if (k2 > best) best = k2;
                k2 = amax_key(vb.x, c0b);     if (k2 > best) best = k2;
                k2 = amax_key(vb.y, c0b + 1); if (k2 > best) best = k2;
                if (has3) {
                    float2 vc = unpack2(acc2[r]);
                    k2 = amax_key(vc.x, c0c);     if (k2 > best) best = k2;
                    k2 = amax_key(vc.y, c0c + 1); if (k2 > best) best = k2;
                }
                kr[r] = best;
            }
            #pragma unroll
            for (int r = 0; r < 8; r++) {
                #pragma unroll
                for (int o = 16; o; o >>= 1) {
                    ull oth = __shfl_xor_sync(0xffffffffu, kr[r], o);
                    if (oth > kr[r]) kr[r] = oth;
                }
            }
            if (lane == 0) {
                #pragma unroll
                for (int r = 0; r < 8; r++) sRed[wid * 8 + r] = kr[r];
            }
            __syncthreads();
            if (tid < 8) {
                ull best = sRed[tid];
                #pragma unroll
                for (int w = 1; w < 8; w++) { ull o = sRed[w * 8 + tid]; if (o > best) best = o; }
                red_max64(&g_keys[s][g][tid], best);
            }
            __syncthreads();
            if (tid == 0) {
                __threadfence();
                if (atomicAdd(&g_gcnt[s][g], 1u) == GSZ - 1) st_rel(&g_gready[s][g], 1u);
            }
        }

        // ================= bulk logits stores (frees acc registers) =================
        #pragma unroll
        for (int r = 0; r < 8; r++) {
            float* orow = out + ((size_t)(g * 8 + r) * S_DE_ + s) * DE_V_ + col0;
            float2 va = unpack2(acc0[r]);
            float2 vb = unpack2(acc1[r]);
            __stcs((float2*)(orow + 2 * tid), va);
            __stcs((float2*)(orow + 2 * (tid + 256)), vb);
            if (has3) {
                float2 vc = unpack2(acc2[r]);
                __stcs((float2*)(orow + 2 * (tid + 512)), vc);
            }
        }

        // ================= group hop: keys -> tokens -> redundant LSTM =================
        if (!last) {
            if (tid == 0) spin_until(&g_gready[s][g]);
            __syncthreads();
            if (tid < 8) {
                ull key = __ldcg(&g_keys[s][g][tid]);
                sTok[tid] = (int)(0xFFFFFFFFu - (unsigned)(key & 0xFFFFFFFFull));
            }
            __syncthreads();
            if (tid < 8 * H_) {                      // x[r][k] = de_emb[tok[r]][k]
                int r = tid >> 5, kk = tid & 31;
                sXf[r * 32 + kk] = de_emb[(size_t)sTok[r] * EMB_D_ + kk];
            }
            __syncthreads();

            // gates: thread (j = tid&127, half = tid>>7) -> 4 rows
            {
                const int j = tid & 127, half = tid >> 7;
                float wtmp[32], a4[4];
                #pragma unroll
                for (int k = 0; k < 32; k++) wtmp[k] = sWih[j * 32 + k];
                #pragma unroll
                for (int rr = 0; rr < 4; rr++) {
                    const int r = half * 4 + rr;
                    float p = 0.0f;
                    #pragma unroll
                    for (int k = 0; k < 32; k++) p += sXf[r * 32 + k] * wtmp[k];
                    a4[rr] = p;
                }
                #pragma unroll
                for (int k = 0; k < 32; k++) wtmp[k] = sWhh[j * 32 + k];
                const float* hF = (const float*)sH2p;
                #pragma unroll
                for (int rr = 0; rr < 4; rr++) {
                    const int r = half * 4 + rr;
                    float p = a4[rr];
                    #pragma unroll
                    for (int k = 0; k < 32; k++) p += hF[(k * 9 + r) * 2] * wtmp[k];
                    sGf[r * 132 + j] = p + sBiasf[j];
                }
            }
            __syncthreads();

            // activation: thread (r = tid>>5, hd = tid&31)
            {
                const int r = tid >> 5, hd = tid & 31;
                float gi = sGf[r * 132 + hd];
                float gf = sGf[r * 132 + 32 + hd];
                float gg = sGf[r * 132 + 64 + hd];
                float go = sGf[r * 132 + 96 + hd];
                float ig = sigmoidf_(gi), fg = sigmoidf_(gf), og = sigmoidf_(go);
                float c  = fg * sCf[r * 32 + hd] + ig * tanhf(gg);
                sCf[r * 32 + hd] = c;
                float h  = og * tanhf(c);
                sH2p[hd * 9 + r] = pack2(h, h);
            }
            __syncthreads();
        }
    }
}

extern "C" void kernel_launch(void* const* d_in, const int* in_sizes, int n_in,
                              void* d_out, int out_size) {
    const int*   en_batch = (const int*)d_in[0];
    const int*   en_lens  = (const int*)d_in[1];
    const int*   de_batch = (const int*)d_in[2];
    const float* en_emb   = (const float*)d_in[3];
    const float* eWih     = (const float*)d_in[4];
    const float* eWhh     = (const float*)d_in[5];
    const float* ebih     = (const float*)d_in[6];
    const float* ebhh     = (const float*)d_in[7];
    const float* de_emb   = (const float*)d_in[8];
    const float* dWih     = (const float*)d_in[9];
    const float* dWhh     = (const float*)d_in[10];
    const float* dbih     = (const float*)d_in[11];
    const float* dbhh     = (const float*)d_in[12];
    const float* fcW      = (const float*)d_in[13];
    const float* fcb      = (const float*)d_in[14];

    static int smem_set = 0;
    if (!smem_set) {
        cudaFuncSetAttribute(seq2seq_kernel,
                             cudaFuncAttributeMaxDynamicSharedMemorySize, SMEM_BYTES);
        smem_set = 1;
    }

    seq2seq_kernel<<<NBLK, NTH, SMEM_BYTES>>>(en_batch, en_lens, de_batch, en_emb,
                                              eWih, eWhh, ebih, ebhh,
                                              de_emb, dWih, dWhh, dbih, dbhh,
                                              fcW, fcb, (float*)d_out);
}